// round 1
// baseline (speedup 1.0000x reference)
#include <cuda_runtime.h>
#include <math.h>
#include <float.h>

// Fixed problem shape: img (16,3,512,512) f32, sbin=4 -> out (16,31,128,128) f32
#define BATCH 16
#define NCH   3
#define IH    512
#define IW    512
#define SBIN  4
#define BH    128
#define BW    128
#define HG    510   // gradient grid height (vh-2)
#define WG    510   // gradient grid width

#define HIST_ELEMS (BATCH * 18 * BH * BW)
#define NORM_ELEMS (BATCH * BH * BW)

__device__ float g_hist[HIST_ELEMS];
__device__ float g_norm[NORM_ELEMS];

__constant__ float c_UU[9] = {1.0f, 0.9397f, 0.766f, 0.5f, 0.1736f,
                              -0.1736f, -0.5f, -0.766f, -0.9397f};
__constant__ float c_VV[9] = {0.0f, 0.342f, 0.6428f, 0.866f, 0.9848f,
                              0.9848f, 0.866f, 0.6428f, 0.342f};

// ---------------------------------------------------------------------------
// Kernel 1: zero the histogram scratch (graph replays must be deterministic)
// ---------------------------------------------------------------------------
__global__ void hog_zero_hist() {
    int idx = blockIdx.x * blockDim.x + threadIdx.x;
    float4* p = reinterpret_cast<float4*>(g_hist);
    int n4 = HIST_ELEMS / 4;
    if (idx < n4) p[idx] = make_float4(0.f, 0.f, 0.f, 0.f);
}

// ---------------------------------------------------------------------------
// Kernel 2: gradients -> orientation -> bilinear scatter into histogram
// ---------------------------------------------------------------------------
__global__ void hog_pixel(const float* __restrict__ img) {
    int idx = blockIdx.x * blockDim.x + threadIdx.x;
    if (idx >= BATCH * HG * WG) return;

    int j = idx % WG;
    int t = idx / WG;
    int i = t % HG;
    int b = t / HG;

    int y = i + 1;   // image row (1..510)
    int x = j + 1;   // image col (1..510)

    const float* base = img + (size_t)b * NCH * IH * IW;

    float bestv = -1.0f, gdx = 0.0f, gdy = 0.0f;
#pragma unroll
    for (int c = 0; c < NCH; c++) {
        const float* p = base + (size_t)c * IH * IW;
        float dy = p[(y + 1) * IW + x] - p[(y - 1) * IW + x];
        float dx = p[y * IW + x + 1] - p[y * IW + x - 1];
        float v = dx * dx + dy * dy;
        if (v > bestv) { bestv = v; gdx = dx; gdy = dy; }
    }
    float mag = sqrtf(bestv);

    // argmax over [dot0..dot8, -dot0..-dot8], first occurrence wins
    float dot[9];
#pragma unroll
    for (int k = 0; k < 9; k++) dot[k] = c_UU[k] * gdx + c_VV[k] * gdy;
    float best = -FLT_MAX;
    int bo = 0;
#pragma unroll
    for (int k = 0; k < 18; k++) {
        float val = (k < 9) ? dot[k] : -dot[k - 9];
        if (val > best) { best = val; bo = k; }
    }

    // bilinear weights into cell grid
    float yp = ((float)y + 0.5f) / (float)SBIN - 0.5f;
    float xp = ((float)x + 0.5f) / (float)SBIN - 0.5f;
    int iy = (int)floorf(yp);
    int ix = (int)floorf(xp);
    float vy0 = yp - (float)iy;
    float vx0 = xp - (float)ix;
    float vy1 = 1.0f - vy0;
    float vx1 = 1.0f - vx0;

    float* hb = g_hist + ((size_t)b * 18 + bo) * (BH * BW);

    if (iy >= 0 && iy < BH) {
        if (ix >= 0 && ix < BW)
            atomicAdd(&hb[iy * BW + ix], vy1 * vx1 * mag);
        if (ix + 1 >= 0 && ix + 1 < BW)
            atomicAdd(&hb[iy * BW + ix + 1], vy1 * vx0 * mag);
    }
    if (iy + 1 >= 0 && iy + 1 < BH) {
        if (ix >= 0 && ix < BW)
            atomicAdd(&hb[(iy + 1) * BW + ix], vy0 * vx1 * mag);
        if (ix + 1 >= 0 && ix + 1 < BW)
            atomicAdd(&hb[(iy + 1) * BW + ix + 1], vy0 * vx0 * mag);
    }
}

// ---------------------------------------------------------------------------
// Kernel 3: per-cell energy norm = sum_{o<9} (hist[o]+hist[o+9])^2
// ---------------------------------------------------------------------------
__global__ void hog_norm() {
    int idx = blockIdx.x * blockDim.x + threadIdx.x;
    if (idx >= NORM_ELEMS) return;
    int cell = idx % (BH * BW);
    int b = idx / (BH * BW);
    const float* hb = g_hist + (size_t)b * 18 * BH * BW + cell;
    float acc = 0.0f;
#pragma unroll
    for (int o = 0; o < 9; o++) {
        float s = hb[o * (BH * BW)] + hb[(o + 9) * (BH * BW)];
        acc += s * s;
    }
    g_norm[idx] = acc;
}

// ---------------------------------------------------------------------------
// Kernel 4: block-normalized features (31 channels) with zero border padding
// ---------------------------------------------------------------------------
__global__ void hog_feat(float* __restrict__ out) {
    int idx = blockIdx.x * blockDim.x + threadIdx.x;
    if (idx >= BATCH * BH * BW) return;
    int j = idx % BW;
    int t = idx / BW;
    int i = t % BH;
    int b = t / BH;

    float* ob = out + (size_t)b * 31 * BH * BW + i * BW + j;

    if (i == 0 || i == BH - 1 || j == 0 || j == BW - 1) {
#pragma unroll
        for (int ch = 0; ch < 31; ch++) ob[ch * (BH * BW)] = 0.0f;
        return;
    }

    const float* nb = g_norm + (size_t)b * BH * BW;
    const float EPS = 0.0001f;
#define NRM(a, c) nb[(a) * BW + (c)]
    float n1 = rsqrtf(NRM(i, j) + NRM(i + 1, j) + NRM(i, j + 1) + NRM(i + 1, j + 1) + EPS);
    float n2 = rsqrtf(NRM(i - 1, j) + NRM(i, j) + NRM(i - 1, j + 1) + NRM(i, j + 1) + EPS);
    float n3 = rsqrtf(NRM(i, j - 1) + NRM(i + 1, j - 1) + NRM(i, j) + NRM(i + 1, j) + EPS);
    float n4 = rsqrtf(NRM(i - 1, j - 1) + NRM(i, j - 1) + NRM(i - 1, j) + NRM(i, j) + EPS);
#undef NRM

    const float* hb = g_hist + (size_t)b * 18 * BH * BW + i * BW + j;

    float src[18];
#pragma unroll
    for (int o = 0; o < 18; o++) src[o] = hb[o * (BH * BW)];

    float t1 = 0.f, t2 = 0.f, t3 = 0.f, t4 = 0.f;
#pragma unroll
    for (int o = 0; o < 18; o++) {
        float h1 = fminf(src[o] * n1, 0.2f);
        float h2 = fminf(src[o] * n2, 0.2f);
        float h3 = fminf(src[o] * n3, 0.2f);
        float h4 = fminf(src[o] * n4, 0.2f);
        t1 += h1; t2 += h2; t3 += h3; t4 += h4;
        ob[o * (BH * BW)] = 0.5f * (h1 + h2 + h3 + h4);
    }
#pragma unroll
    for (int o = 0; o < 9; o++) {
        float ss = src[o] + src[o + 9];
        float v = fminf(ss * n1, 0.2f) + fminf(ss * n2, 0.2f) +
                  fminf(ss * n3, 0.2f) + fminf(ss * n4, 0.2f);
        ob[(18 + o) * (BH * BW)] = 0.5f * v;
    }
    ob[27 * (BH * BW)] = 0.2357f * t1;
    ob[28 * (BH * BW)] = 0.2357f * t2;
    ob[29 * (BH * BW)] = 0.2357f * t3;
    ob[30 * (BH * BW)] = 0.2357f * t4;
}

// ---------------------------------------------------------------------------
extern "C" void kernel_launch(void* const* d_in, const int* in_sizes, int n_in,
                              void* d_out, int out_size) {
    const float* img = (const float*)d_in[0];
    float* out = (float*)d_out;

    {
        int n4 = HIST_ELEMS / 4;
        hog_zero_hist<<<(n4 + 255) / 256, 256>>>();
    }
    {
        int n = BATCH * HG * WG;
        hog_pixel<<<(n + 255) / 256, 256>>>(img);
    }
    {
        int n = NORM_ELEMS;
        hog_norm<<<(n + 255) / 256, 256>>>();
    }
    {
        int n = BATCH * BH * BW;
        hog_feat<<<(n + 255) / 256, 256>>>(out);
    }
}

// round 2
// speedup vs baseline: 1.4596x; 1.4596x over previous
#include <cuda_runtime.h>
#include <math.h>
#include <float.h>

// Fixed problem shape: img (16,3,512,512) f32, sbin=4 -> out (16,31,128,128) f32
#define BATCH 16
#define NCH   3
#define IH    512
#define IW    512
#define SBIN  4
#define BH    128
#define BW    128

#define TS    16          // cells per tile side
#define PW    68          // pixel window side: 4*TS + 4
#define MPITCH 69         // padded pitch for s_mag

#define HIST_ELEMS (BATCH * 18 * BH * BW)
#define NORM_ELEMS (BATCH * BH * BW)

__device__ float g_hist[HIST_ELEMS];
__device__ float g_norm[NORM_ELEMS];

__constant__ float c_UU[9] = {1.0f, 0.9397f, 0.766f, 0.5f, 0.1736f,
                              -0.1736f, -0.5f, -0.766f, -0.9397f};
__constant__ float c_VV[9] = {0.0f, 0.342f, 0.6428f, 0.866f, 0.9848f,
                              0.9848f, 0.866f, 0.6428f, 0.342f};

// ---------------------------------------------------------------------------
// Kernel 1 (fused): gradients + orientation + per-cell gather + norm.
// One block = 16x16 cells of one batch image. No global atomics.
// ---------------------------------------------------------------------------
__global__ __launch_bounds__(256) void hog_gather(const float* __restrict__ img) {
    __shared__ float         s_mag[PW * MPITCH];
    __shared__ unsigned char s_bo[PW * PW];
    __shared__ float         s_bins[18 * 256];

    const int tid = threadIdx.x;
    const int cx0 = blockIdx.x * TS;       // first cell col of tile
    const int cy0 = blockIdx.y * TS;       // first cell row of tile
    const int b   = blockIdx.z;

    const int x0 = 4 * cx0 - 2;            // image col of window origin
    const int y0 = 4 * cy0 - 2;            // image row of window origin

    const float* base = img + (size_t)b * NCH * IH * IW;

    // ---- Stage 1: per-pixel gradient / orientation into smem ----
    for (int p = tid; p < PW * PW; p += 256) {
        int py = p / PW;
        int px = p - py * PW;
        int y  = y0 + py;
        int x  = x0 + px;

        float mag = 0.0f;
        int   bo  = 0;

        if (y >= 1 && y <= IH - 2 && x >= 1 && x <= IW - 2) {
            float bestv = -1.0f, gdx = 0.0f, gdy = 0.0f;
#pragma unroll
            for (int c = 0; c < NCH; c++) {
                const float* pp = base + (size_t)c * IH * IW;
                float dy = pp[(y + 1) * IW + x] - pp[(y - 1) * IW + x];
                float dx = pp[y * IW + x + 1] - pp[y * IW + x - 1];
                float v  = dx * dx + dy * dy;
                if (v > bestv) { bestv = v; gdx = dx; gdy = dy; }
            }
            mag = sqrtf(bestv);

            // argmax over [d0..d8, -d0..-d8], first occurrence wins.
            // max over positives = (maxv, maxi); max over negatives = (-minv, mini).
            float maxv = -FLT_MAX, minv = FLT_MAX;
            int   maxi = 0,        mini = 0;
#pragma unroll
            for (int k = 0; k < 9; k++) {
                float d = c_UU[k] * gdx + c_VV[k] * gdy;
                if (d > maxv) { maxv = d; maxi = k; }
                if (d < minv) { minv = d; mini = k; }
            }
            bo = (maxv >= -minv) ? maxi : mini + 9;
        }
        s_mag[py * MPITCH + px] = mag;
        s_bo[p] = (unsigned char)bo;
    }

    // ---- Stage 2: zero per-thread bins ----
#pragma unroll
    for (int o = 0; o < 18; o++) s_bins[o * 256 + tid] = 0.0f;

    __syncthreads();

    // ---- Stage 3: gather 8x8 pixel footprint per cell ----
    // Separable weights: wy = 1 - |dy-3.5|/4 -> {.125,.375,.625,.875,.875,.625,.375,.125}
    const int lcy = tid >> 4;
    const int lcx = tid & 15;
    const int prow = 4 * lcy;
    const int pcol = 4 * lcx;

#pragma unroll
    for (int dy = 0; dy < 8; dy++) {
        const float wy = (dy < 4) ? (0.125f + 0.25f * dy) : (0.875f - 0.25f * (dy - 4));
        const float* mrow = &s_mag[(prow + dy) * MPITCH + pcol];
        const unsigned char* brow = &s_bo[(prow + dy) * PW + pcol];
#pragma unroll
        for (int dx = 0; dx < 8; dx++) {
            const float wx = (dx < 4) ? (0.125f + 0.25f * dx) : (0.875f - 0.25f * (dx - 4));
            float m = mrow[dx] * (wy * wx);
            int o = brow[dx];
            s_bins[o * 256 + tid] += m;
        }
    }

    // ---- Stage 4: write hist + norm (plain coalesced stores) ----
    const int cy = cy0 + lcy;
    const int cx = cx0 + lcx;
    float* hb = g_hist + ((size_t)b * 18) * (BH * BW) + cy * BW + cx;

    float acc = 0.0f;
#pragma unroll
    for (int o = 0; o < 9; o++) {
        float a = s_bins[o * 256 + tid];
        float c = s_bins[(o + 9) * 256 + tid];
        hb[o * (BH * BW)]       = a;
        hb[(o + 9) * (BH * BW)] = c;
        float s = a + c;
        acc += s * s;
    }
    g_norm[(size_t)b * BH * BW + cy * BW + cx] = acc;
}

// ---------------------------------------------------------------------------
// Kernel 2: block-normalized features (31 channels) with zero border padding
// ---------------------------------------------------------------------------
__global__ void hog_feat(float* __restrict__ out) {
    int idx = blockIdx.x * blockDim.x + threadIdx.x;
    if (idx >= BATCH * BH * BW) return;
    int j = idx % BW;
    int t = idx / BW;
    int i = t % BH;
    int b = t / BH;

    float* ob = out + (size_t)b * 31 * BH * BW + i * BW + j;

    if (i == 0 || i == BH - 1 || j == 0 || j == BW - 1) {
#pragma unroll
        for (int ch = 0; ch < 31; ch++) ob[ch * (BH * BW)] = 0.0f;
        return;
    }

    const float* nb = g_norm + (size_t)b * BH * BW;
    const float EPS = 0.0001f;
#define NRM(a, c) nb[(a) * BW + (c)]
    float n1 = rsqrtf(NRM(i, j) + NRM(i + 1, j) + NRM(i, j + 1) + NRM(i + 1, j + 1) + EPS);
    float n2 = rsqrtf(NRM(i - 1, j) + NRM(i, j) + NRM(i - 1, j + 1) + NRM(i, j + 1) + EPS);
    float n3 = rsqrtf(NRM(i, j - 1) + NRM(i + 1, j - 1) + NRM(i, j) + NRM(i + 1, j) + EPS);
    float n4 = rsqrtf(NRM(i - 1, j - 1) + NRM(i, j - 1) + NRM(i - 1, j) + NRM(i, j) + EPS);
#undef NRM

    const float* hb = g_hist + (size_t)b * 18 * BH * BW + i * BW + j;

    float src[18];
#pragma unroll
    for (int o = 0; o < 18; o++) src[o] = hb[o * (BH * BW)];

    float t1 = 0.f, t2 = 0.f, t3 = 0.f, t4 = 0.f;
#pragma unroll
    for (int o = 0; o < 18; o++) {
        float h1 = fminf(src[o] * n1, 0.2f);
        float h2 = fminf(src[o] * n2, 0.2f);
        float h3 = fminf(src[o] * n3, 0.2f);
        float h4 = fminf(src[o] * n4, 0.2f);
        t1 += h1; t2 += h2; t3 += h3; t4 += h4;
        ob[o * (BH * BW)] = 0.5f * (h1 + h2 + h3 + h4);
    }
#pragma unroll
    for (int o = 0; o < 9; o++) {
        float ss = src[o] + src[o + 9];
        float v = fminf(ss * n1, 0.2f) + fminf(ss * n2, 0.2f) +
                  fminf(ss * n3, 0.2f) + fminf(ss * n4, 0.2f);
        ob[(18 + o) * (BH * BW)] = 0.5f * v;
    }
    ob[27 * (BH * BW)] = 0.2357f * t1;
    ob[28 * (BH * BW)] = 0.2357f * t2;
    ob[29 * (BH * BW)] = 0.2357f * t3;
    ob[30 * (BH * BW)] = 0.2357f * t4;
}

// ---------------------------------------------------------------------------
extern "C" void kernel_launch(void* const* d_in, const int* in_sizes, int n_in,
                              void* d_out, int out_size) {
    const float* img = (const float*)d_in[0];
    float* out = (float*)d_out;

    dim3 grid(BW / TS, BH / TS, BATCH);   // (8, 8, 16)
    hog_gather<<<grid, 256>>>(img);

    int n = BATCH * BH * BW;
    hog_feat<<<(n + 255) / 256, 256>>>(out);
}

// round 3
// speedup vs baseline: 1.8442x; 1.2635x over previous
#include <cuda_runtime.h>
#include <math.h>
#include <float.h>

// Fixed problem shape: img (16,3,512,512) f32, sbin=4 -> out (16,31,128,128) f32
#define BATCH 16
#define NCH   3
#define IH    512
#define IW    512
#define BH    128
#define BW    128

#define TS     16         // cells per tile side
#define WROWS  68         // pixel rows in window
#define WCOLS  68         // used pixel cols (sc 0..67)
#define MP     72         // smem pitch (floats for mag, bytes for bo)
#define NSTRIP 18         // 4-px strips per row (covers sc -2..69)

#define HIST_ELEMS (BATCH * 18 * BH * BW)
#define NORM_ELEMS (BATCH * BH * BW)

__device__ float g_hist[HIST_ELEMS];
__device__ float g_norm[NORM_ELEMS];

// ---------------------------------------------------------------------------
// Kernel 1 (fused): gradients + orientation + per-cell gather + norm.
// One block = 16x16 cells of one batch image. No atomics anywhere.
// ---------------------------------------------------------------------------
__global__ __launch_bounds__(256, 2) void hog_gather(const float* __restrict__ img) {
    __shared__ float         s_mag[WROWS * MP];   // 19584 B
    __shared__ unsigned char s_bo[WROWS * MP];    //  4896 B
    __shared__ float         s_bins[18 * 256];    // 18432 B

    const int tid = threadIdx.x;
    const int cx0 = blockIdx.x * TS;
    const int cy0 = blockIdx.y * TS;
    const int b   = blockIdx.z;

    const int y0  = 4 * cy0 - 2;        // image row of window row 0
    const int x0a = 4 * cx0 - 4;        // ALIGNED image col of strip 0
    // smem col sc = image_x - (4*cx0 - 2)

    const float* base = img + (size_t)b * NCH * IH * IW;

    const float UU[9] = {1.0f, 0.9397f, 0.766f, 0.5f, 0.1736f,
                         -0.1736f, -0.5f, -0.766f, -0.9397f};
    const float VV[9] = {0.0f, 0.342f, 0.6428f, 0.866f, 0.9848f,
                         0.9848f, 0.866f, 0.6428f, 0.342f};

    // ---- zero per-thread bins (before the sync) ----
#pragma unroll
    for (int o = 0; o < 18; o++) s_bins[o * 256 + tid] = 0.0f;

    // ---- Stage 1: per-pixel gradient / orientation, 4-px strips ----
    for (int t = tid; t < NSTRIP * WROWS; t += 256) {
        const int s  = t % NSTRIP;
        const int py = t / NSTRIP;
        const int y  = y0 + py;
        const int xb = x0a + 4 * s;              // aligned (mult of 4)

        float mag[4];
        int   bo[4];

        if (y >= 1 && y <= IH - 2) {
            float bestv[4] = {-1.f, -1.f, -1.f, -1.f};
            float bdx[4], bdy[4];
#pragma unroll
            for (int c = 0; c < NCH; c++) {
                const float* rp = base + (size_t)c * IH * IW + (size_t)y * IW + xb;
                float4 up = *reinterpret_cast<const float4*>(rp - IW);
                float4 dn = *reinterpret_cast<const float4*>(rp + IW);
                float4 md = *reinterpret_cast<const float4*>(rp);
                float  lf = rp[-1];
                float  rt = rp[4];
                float mx[6] = {lf, md.x, md.y, md.z, md.w, rt};
                float u[4] = {up.x, up.y, up.z, up.w};
                float d[4] = {dn.x, dn.y, dn.z, dn.w};
#pragma unroll
                for (int i = 0; i < 4; i++) {
                    float gdy = d[i] - u[i];
                    float gdx = mx[i + 2] - mx[i];
                    float v = gdx * gdx + gdy * gdy;
                    if (v > bestv[i]) { bestv[i] = v; bdx[i] = gdx; bdy[i] = gdy; }
                }
            }
#pragma unroll
            for (int i = 0; i < 4; i++) {
                float maxv = -FLT_MAX, minv = FLT_MAX;
                int   maxi = 0,        mini = 0;
#pragma unroll
                for (int k = 0; k < 9; k++) {
                    float dd = UU[k] * bdx[i] + VV[k] * bdy[i];
                    if (dd > maxv) { maxv = dd; maxi = k; }
                    if (dd < minv) { minv = dd; mini = k; }
                }
                bo[i]  = (maxv >= -minv) ? maxi : mini + 9;
                mag[i] = (bestv[i] > 0.f) ? bestv[i] * rsqrtf(bestv[i]) : 0.f;
                int x = xb + i;
                if (x < 1 || x > IW - 2) mag[i] = 0.f;
            }
        } else {
#pragma unroll
            for (int i = 0; i < 4; i++) { mag[i] = 0.f; bo[i] = 0; }
        }

#pragma unroll
        for (int i = 0; i < 4; i++) {
            int sc = 4 * s - 2 + i;
            if (sc >= 0 && sc < WCOLS) {
                s_mag[py * MP + sc] = mag[i];
                s_bo[py * MP + sc]  = (unsigned char)bo[i];
            }
        }
    }

    __syncthreads();

    // ---- Stage 3: gather 8x8 pixel footprint per cell ----
    const int lcy = tid >> 4;
    const int lcx = tid & 15;
    const int pr  = 4 * lcy;
    const int pc  = 4 * lcx;

    const float W8[8] = {0.125f, 0.375f, 0.625f, 0.875f,
                         0.875f, 0.625f, 0.375f, 0.125f};

#pragma unroll
    for (int dy = 0; dy < 8; dy++) {
        const float wy = W8[dy];
        const int row = pr + dy;
        float4 m0 = *reinterpret_cast<const float4*>(&s_mag[row * MP + pc]);
        float4 m1 = *reinterpret_cast<const float4*>(&s_mag[row * MP + pc + 4]);
        unsigned int u0 = *reinterpret_cast<const unsigned int*>(&s_bo[row * MP + pc]);
        unsigned int u1 = *reinterpret_cast<const unsigned int*>(&s_bo[row * MP + pc + 4]);
        float mm[8] = {m0.x, m0.y, m0.z, m0.w, m1.x, m1.y, m1.z, m1.w};
#pragma unroll
        for (int dx = 0; dx < 8; dx++) {
            unsigned int u = (dx < 4) ? u0 : u1;
            int o = (u >> (8 * (dx & 3))) & 0xFF;
            s_bins[o * 256 + tid] += mm[dx] * (wy * W8[dx]);
        }
    }

    // ---- Stage 4: write hist + norm (coalesced stores) ----
    const int cy = cy0 + lcy;
    const int cx = cx0 + lcx;
    float* hb = g_hist + ((size_t)b * 18) * (BH * BW) + cy * BW + cx;

    float acc = 0.0f;
#pragma unroll
    for (int o = 0; o < 9; o++) {
        float a = s_bins[o * 256 + tid];
        float c = s_bins[(o + 9) * 256 + tid];
        hb[o * (BH * BW)]       = a;
        hb[(o + 9) * (BH * BW)] = c;
        float s = a + c;
        acc += s * s;
    }
    g_norm[(size_t)b * BH * BW + cy * BW + cx] = acc;
}

// ---------------------------------------------------------------------------
// Kernel 2: block-normalized features, 2 px per thread (float2 I/O)
// ---------------------------------------------------------------------------
__global__ __launch_bounds__(256, 2) void hog_feat(float* __restrict__ out) {
    int idx = blockIdx.x * blockDim.x + threadIdx.x;
    if (idx >= BATCH * BH * (BW / 2)) return;
    const int j2 = idx & 63;
    int t = idx >> 6;
    const int i = t & (BH - 1);
    const int b = t >> 7;
    const int j = 2 * j2;

    float* ob = out + (size_t)b * 31 * BH * BW + i * BW + j;

    if (i == 0 || i == BH - 1) {
        const float2 z = make_float2(0.f, 0.f);
#pragma unroll
        for (int ch = 0; ch < 31; ch++)
            *reinterpret_cast<float2*>(&ob[ch * (BH * BW)]) = z;
        return;
    }

    const bool v0 = (j >= 1);            // element 0 interior?
    const bool v1 = (j + 1 <= BW - 2);   // element 1 interior?

    const float* nb = g_norm + (size_t)b * BH * BW;
    const int jm1 = (j >= 1) ? j - 1 : 0;
    const int jp2 = (j + 2 <= BW - 1) ? j + 2 : BW - 1;

    float r0[4], r1[4], r2[4];
    {
        const float* p = &nb[(i - 1) * BW];
        float2 v = *reinterpret_cast<const float2*>(&p[j]);
        r0[0] = p[jm1]; r0[1] = v.x; r0[2] = v.y; r0[3] = p[jp2];
    }
    {
        const float* p = &nb[i * BW];
        float2 v = *reinterpret_cast<const float2*>(&p[j]);
        r1[0] = p[jm1]; r1[1] = v.x; r1[2] = v.y; r1[3] = p[jp2];
    }
    {
        const float* p = &nb[(i + 1) * BW];
        float2 v = *reinterpret_cast<const float2*>(&p[j]);
        r2[0] = p[jm1]; r2[1] = v.x; r2[2] = v.y; r2[3] = p[jp2];
    }

    const float EPS = 0.0001f;
    float n1[2], n2[2], n3[2], n4[2];
#pragma unroll
    for (int e = 0; e < 2; e++) {
        n1[e] = rsqrtf(r1[e + 1] + r2[e + 1] + r1[e + 2] + r2[e + 2] + EPS);
        n2[e] = rsqrtf(r0[e + 1] + r1[e + 1] + r0[e + 2] + r1[e + 2] + EPS);
        n3[e] = rsqrtf(r1[e] + r2[e] + r1[e + 1] + r2[e + 1] + EPS);
        n4[e] = rsqrtf(r0[e] + r1[e] + r0[e + 1] + r1[e + 1] + EPS);
    }

    const float* hb = g_hist + (size_t)b * 18 * BH * BW + i * BW + j;
    float2 src[18];
#pragma unroll
    for (int o = 0; o < 18; o++)
        src[o] = *reinterpret_cast<const float2*>(&hb[o * (BH * BW)]);

    float t1[2] = {0.f, 0.f}, t2[2] = {0.f, 0.f},
          t3[2] = {0.f, 0.f}, t4[2] = {0.f, 0.f};

#pragma unroll
    for (int o = 0; o < 18; o++) {
        float2 res;
        {
            float s = src[o].x;
            float h1 = fminf(s * n1[0], 0.2f);
            float h2 = fminf(s * n2[0], 0.2f);
            float h3 = fminf(s * n3[0], 0.2f);
            float h4 = fminf(s * n4[0], 0.2f);
            t1[0] += h1; t2[0] += h2; t3[0] += h3; t4[0] += h4;
            res.x = v0 ? 0.5f * (h1 + h2 + h3 + h4) : 0.f;
        }
        {
            float s = src[o].y;
            float h1 = fminf(s * n1[1], 0.2f);
            float h2 = fminf(s * n2[1], 0.2f);
            float h3 = fminf(s * n3[1], 0.2f);
            float h4 = fminf(s * n4[1], 0.2f);
            t1[1] += h1; t2[1] += h2; t3[1] += h3; t4[1] += h4;
            res.y = v1 ? 0.5f * (h1 + h2 + h3 + h4) : 0.f;
        }
        *reinterpret_cast<float2*>(&ob[o * (BH * BW)]) = res;
    }
#pragma unroll
    for (int o = 0; o < 9; o++) {
        float2 res;
        {
            float ss = src[o].x + src[o + 9].x;
            float v = fminf(ss * n1[0], 0.2f) + fminf(ss * n2[0], 0.2f) +
                      fminf(ss * n3[0], 0.2f) + fminf(ss * n4[0], 0.2f);
            res.x = v0 ? 0.5f * v : 0.f;
        }
        {
            float ss = src[o].y + src[o + 9].y;
            float v = fminf(ss * n1[1], 0.2f) + fminf(ss * n2[1], 0.2f) +
                      fminf(ss * n3[1], 0.2f) + fminf(ss * n4[1], 0.2f);
            res.y = v1 ? 0.5f * v : 0.f;
        }
        *reinterpret_cast<float2*>(&ob[(18 + o) * (BH * BW)]) = res;
    }
    {
        float2 r27 = make_float2(v0 ? 0.2357f * t1[0] : 0.f, v1 ? 0.2357f * t1[1] : 0.f);
        float2 r28 = make_float2(v0 ? 0.2357f * t2[0] : 0.f, v1 ? 0.2357f * t2[1] : 0.f);
        float2 r29 = make_float2(v0 ? 0.2357f * t3[0] : 0.f, v1 ? 0.2357f * t3[1] : 0.f);
        float2 r30 = make_float2(v0 ? 0.2357f * t4[0] : 0.f, v1 ? 0.2357f * t4[1] : 0.f);
        *reinterpret_cast<float2*>(&ob[27 * (BH * BW)]) = r27;
        *reinterpret_cast<float2*>(&ob[28 * (BH * BW)]) = r28;
        *reinterpret_cast<float2*>(&ob[29 * (BH * BW)]) = r29;
        *reinterpret_cast<float2*>(&ob[30 * (BH * BW)]) = r30;
    }
}

// ---------------------------------------------------------------------------
extern "C" void kernel_launch(void* const* d_in, const int* in_sizes, int n_in,
                              void* d_out, int out_size) {
    const float* img = (const float*)d_in[0];
    float* out = (float*)d_out;

    dim3 grid(BW / TS, BH / TS, BATCH);   // (8, 8, 16)
    hog_gather<<<grid, 256>>>(img);

    int n = BATCH * BH * (BW / 2);
    hog_feat<<<(n + 255) / 256, 256>>>(out);
}